// round 15
// baseline (speedup 1.0000x reference)
#include <cuda_runtime.h>
#include <math.h>

#define BB 2048
#define KK 8
#define OO 256
#define II 512

#define G  8              // o's per block (one warp each)
#define OT (OO / G)       // 32 o-tiles
#define P  8              // b-slices per (k, o-tile)  (measured optimum)

// Scratch (no allocs allowed)
__device__ int g_cnt[KK];
__device__ int g_list[KK][BB];

// ---------------------------------------------------------------------------
// 1) argmax of gumbel-perturbed logits (== hard gumbel-softmax forward
//    one-hot) + per-k compaction. 1024 threads (2 rows each). Fires the PDL
//    trigger IMMEDIATELY so main_kernel's blocks launch and run their
//    sel-independent prologue concurrently with this whole kernel.
// ---------------------------------------------------------------------------
__global__ __launch_bounds__(1024)
void sel_kernel(const float* __restrict__ mw,
                const float* __restrict__ u) {
    // Let the dependent (PDL) kernel begin launching right away; its
    // cudaGridDependencySynchronize() still waits for our completion.
    cudaTriggerProgrammaticLaunchCompletion();

    __shared__ int scnt[KK];
    const int tid = threadIdx.x;
    if (tid < KK) scnt[tid] = 0;
    __syncthreads();

    int myk[BB / 1024], mypos[BB / 1024];
#pragma unroll
    for (int r = 0; r < BB / 1024; r++) {
        const int b = tid + 1024 * r;
        float best = -INFINITY;
        int   bi   = 0;
#pragma unroll
        for (int k = 0; k < KK; k++) {
            float uv = u[b * KK + k];
            float g  = -logf(-logf(uv + 1e-10f) + 1e-10f);
            float v  = mw[k] + g;
            if (v > best) { best = v; bi = k; }   // strict > == first max (jnp.argmax)
        }
        myk[r]   = bi;
        mypos[r] = atomicAdd(&scnt[bi], 1);
    }
    __syncthreads();

#pragma unroll
    for (int r = 0; r < BB / 1024; r++)
        g_list[myk[r]][mypos[r]] = tid + 1024 * r;
    if (tid < KK) g_cnt[tid] = scnt[tid];
}

// ---------------------------------------------------------------------------
// 2) out[b,o] = sum_i X[b,i] * fmaf(exp(ls[k,o,i]), eps[b,o,i], mean[k,o,i])
//    Measured-optimal structure: 120 regs, occ 2, staged X arrays, b-pairs
//    with 8 eps LDG.128 batched, dual 5-level butterfly reduce, g_list
//    index prefetch. eps via __ldcs; out via __stcs; PDL gates g_cnt/g_list.
// ---------------------------------------------------------------------------
__global__ __launch_bounds__(256, 2)
void main_kernel(const float* __restrict__ X,
                 const float* __restrict__ mean,
                 const float* __restrict__ ls,
                 const float* __restrict__ eps,
                 float*       __restrict__ out) {
    const int blk   = blockIdx.x;
    const int slice = blk % P;
    const int ot    = (blk / P) % OT;
    const int k     = blk / (P * OT);

    const int warp = threadIdx.x >> 5;
    const int lane = threadIdx.x & 31;
    const int o    = ot * G + warp;

    // ---- sel-independent prologue: overlaps with sel_kernel via PDL ----
    const size_t rbase = ((size_t)k * OO + o) * II;
    const float4* mrow = reinterpret_cast<const float4*>(mean + rbase);
    const float4* lrow = reinterpret_cast<const float4*>(ls   + rbase);
    float4 mv[4], sv[4];
#pragma unroll
    for (int j = 0; j < 4; j++) {
        mv[j] = mrow[lane + 32 * j];
        float4 l4 = lrow[lane + 32 * j];
        sv[j].x = expf(l4.x); sv[j].y = expf(l4.y);
        sv[j].z = expf(l4.z); sv[j].w = expf(l4.w);
    }

    // ---- wait for sel_kernel's g_cnt/g_list to be visible ----
    cudaGridDependencySynchronize();

    const int cnt   = g_cnt[k];
    const int start = (int)((long long)cnt * slice / P);
    const int end   = (int)((long long)cnt * (slice + 1) / P);
    int idx = start;

    // Odd-length remainder: one single-b iteration.
    if ((end - start) & 1) {
        const int b = g_list[k][idx++];
        const float4* ev = reinterpret_cast<const float4*>(eps + ((size_t)b * OO + o) * II);
        const float4* Xv = reinterpret_cast<const float4*>(X   + (size_t)b * II);
        float4 e4[4], x4[4];
#pragma unroll
        for (int j = 0; j < 4; j++) e4[j] = __ldcs(&ev[lane + 32 * j]);
#pragma unroll
        for (int j = 0; j < 4; j++) x4[j] = Xv[lane + 32 * j];
        float acc = 0.f;
#pragma unroll
        for (int j = 0; j < 4; j++) {
            acc = fmaf(x4[j].x, fmaf(sv[j].x, e4[j].x, mv[j].x), acc);
            acc = fmaf(x4[j].y, fmaf(sv[j].y, e4[j].y, mv[j].y), acc);
            acc = fmaf(x4[j].z, fmaf(sv[j].z, e4[j].z, mv[j].z), acc);
            acc = fmaf(x4[j].w, fmaf(sv[j].w, e4[j].w, mv[j].w), acc);
        }
#pragma unroll
        for (int off = 16; off; off >>= 1)
            acc += __shfl_xor_sync(0xffffffffu, acc, off);
        if (lane == 0) __stcs(&out[(size_t)b * OO + o], acc);
    }

    // Main pairs with index prefetch: 8 eps LDG.128 in flight per warp.
    int b0 = 0, b1 = 0;
    if (idx < end) { b0 = g_list[k][idx]; b1 = g_list[k][idx + 1]; }

    for (; idx < end; idx += 2) {
        const float4* e0 = reinterpret_cast<const float4*>(eps + ((size_t)b0 * OO + o) * II);
        const float4* e1 = reinterpret_cast<const float4*>(eps + ((size_t)b1 * OO + o) * II);
        const float4* x0 = reinterpret_cast<const float4*>(X   + (size_t)b0 * II);
        const float4* x1 = reinterpret_cast<const float4*>(X   + (size_t)b1 * II);

        float4 ea[4], eb[4], xa[4], xb[4];
#pragma unroll
        for (int j = 0; j < 4; j++) ea[j] = __ldcs(&e0[lane + 32 * j]);  // DRAM, evict-first
#pragma unroll
        for (int j = 0; j < 4; j++) eb[j] = __ldcs(&e1[lane + 32 * j]);  // DRAM, evict-first
#pragma unroll
        for (int j = 0; j < 4; j++) xa[j] = x0[lane + 32 * j];           // L1-resident
#pragma unroll
        for (int j = 0; j < 4; j++) xb[j] = x1[lane + 32 * j];           // L1-resident

        const int bc0 = b0, bc1 = b1;
        // Prefetch next pair's indices during the FMA phase.
        if (idx + 2 < end) { b0 = g_list[k][idx + 2]; b1 = g_list[k][idx + 3]; }

        float acc0 = 0.f, acc1 = 0.f;
#pragma unroll
        for (int j = 0; j < 4; j++) {
            acc0 = fmaf(xa[j].x, fmaf(sv[j].x, ea[j].x, mv[j].x), acc0);
            acc1 = fmaf(xb[j].x, fmaf(sv[j].x, eb[j].x, mv[j].x), acc1);
            acc0 = fmaf(xa[j].y, fmaf(sv[j].y, ea[j].y, mv[j].y), acc0);
            acc1 = fmaf(xb[j].y, fmaf(sv[j].y, eb[j].y, mv[j].y), acc1);
            acc0 = fmaf(xa[j].z, fmaf(sv[j].z, ea[j].z, mv[j].z), acc0);
            acc1 = fmaf(xb[j].z, fmaf(sv[j].z, eb[j].z, mv[j].z), acc1);
            acc0 = fmaf(xa[j].w, fmaf(sv[j].w, ea[j].w, mv[j].w), acc0);
            acc1 = fmaf(xb[j].w, fmaf(sv[j].w, eb[j].w, mv[j].w), acc1);
        }
#pragma unroll
        for (int off = 16; off; off >>= 1) {
            acc0 += __shfl_xor_sync(0xffffffffu, acc0, off);
            acc1 += __shfl_xor_sync(0xffffffffu, acc1, off);
        }
        if (lane == 0) {
            __stcs(&out[(size_t)bc0 * OO + o], acc0);
            __stcs(&out[(size_t)bc1 * OO + o], acc1);
        }
    }
}

// ---------------------------------------------------------------------------
// Inputs (metadata order): X[B,I], mix_weights[K], mean[K,O,I],
//                          log_sigma[K,O,I], u_gumbel[B,K], eps[B,O,I]
// Output: float32 [B,O]
// ---------------------------------------------------------------------------
extern "C" void kernel_launch(void* const* d_in, const int* in_sizes, int n_in,
                              void* d_out, int out_size) {
    const float* X    = (const float*)d_in[0];
    const float* mw   = (const float*)d_in[1];
    const float* mean = (const float*)d_in[2];
    const float* ls   = (const float*)d_in[3];
    const float* u    = (const float*)d_in[4];
    const float* eps  = (const float*)d_in[5];
    float* out        = (float*)d_out;

    sel_kernel<<<1, 1024>>>(mw, u);

    // PDL launch: main starts while sel runs (sel triggers immediately);
    // prologue overlaps, body gated by cudaGridDependencySynchronize().
    cudaLaunchConfig_t cfg = {};
    cfg.gridDim  = dim3(KK * OT * P);
    cfg.blockDim = dim3(256);
    cudaLaunchAttribute attr[1];
    attr[0].id = cudaLaunchAttributeProgrammaticStreamSerialization;
    attr[0].val.programmaticStreamSerializationAllowed = 1;
    cfg.attrs    = attr;
    cfg.numAttrs = 1;
    cudaLaunchKernelEx(&cfg, main_kernel, X, mean, ls, eps, out);
}

// round 16
// speedup vs baseline: 1.0135x; 1.0135x over previous
#include <cuda_runtime.h>
#include <math.h>

#define BB 2048
#define KK 8
#define OO 256
#define II 512

#define G  8              // o's per block (one warp each)
#define OT (OO / G)       // 32 o-tiles
#define P  8              // b-slices per (k, o-tile)  (measured optimum)

// Scratch (no allocs allowed)
__device__ int g_cnt[KK];
__device__ int g_list[KK][BB];

// ---------------------------------------------------------------------------
// 1) Selection + per-k compaction.
//    Hard gumbel-softmax forward value is exactly one_hot(argmax_k(mw[k]+g_k)).
//    FAST PATH: mix_weights is constant (reference uses full(1/K)), and
//    g(u) = -log(-log(u+TINY)+TINY) is strictly increasing in u, so
//    argmax_k(mw+g) == argmax_k u[b,k] -- no logarithms at all. The exact
//    gumbel computation remains as fallback for non-uniform mw.
// ---------------------------------------------------------------------------
__global__ __launch_bounds__(1024)
void sel_kernel(const float* __restrict__ mw,
                const float* __restrict__ u) {
    __shared__ int scnt[KK];
    const int tid = threadIdx.x;
    if (tid < KK) scnt[tid] = 0;

    // All-equal check on mw (8 values, L1-broadcast).
    float m0 = mw[0];
    bool uniform = true;
#pragma unroll
    for (int k = 1; k < KK; k++) uniform &= (mw[k] == m0);

    __syncthreads();

    int myk[BB / 1024], mypos[BB / 1024];
#pragma unroll
    for (int r = 0; r < BB / 1024; r++) {
        const int b = tid + 1024 * r;
        int bi = 0;
        if (uniform) {
            // Monotone shortcut: argmax of raw uniforms (strict > == first max).
            float best = -INFINITY;
#pragma unroll
            for (int k = 0; k < KK; k++) {
                float uv = u[b * KK + k];
                if (uv > best) { best = uv; bi = k; }
            }
        } else {
            float best = -INFINITY;
#pragma unroll
            for (int k = 0; k < KK; k++) {
                float uv = u[b * KK + k];
                float g  = -logf(-logf(uv + 1e-10f) + 1e-10f);
                float v  = mw[k] + g;
                if (v > best) { best = v; bi = k; }
            }
        }
        myk[r]   = bi;
        mypos[r] = atomicAdd(&scnt[bi], 1);
    }
    __syncthreads();

#pragma unroll
    for (int r = 0; r < BB / 1024; r++)
        g_list[myk[r]][mypos[r]] = tid + 1024 * r;
    if (tid < KK) g_cnt[tid] = scnt[tid];
}

// ---------------------------------------------------------------------------
// 2) out[b,o] = sum_i X[b,i] * fmaf(exp(ls[k,o,i]), eps[b,o,i], mean[k,o,i])
//    Measured-optimal structure: 120 regs, occ 2, staged X arrays, b-pairs
//    with 8 eps LDG.128 batched, dual 5-level butterfly reduce, g_list
//    index prefetch. eps via __ldcs; out via __stcs; PDL gates g_cnt/g_list.
// ---------------------------------------------------------------------------
__global__ __launch_bounds__(256, 2)
void main_kernel(const float* __restrict__ X,
                 const float* __restrict__ mean,
                 const float* __restrict__ ls,
                 const float* __restrict__ eps,
                 float*       __restrict__ out) {
    const int blk   = blockIdx.x;
    const int slice = blk % P;
    const int ot    = (blk / P) % OT;
    const int k     = blk / (P * OT);

    const int warp = threadIdx.x >> 5;
    const int lane = threadIdx.x & 31;
    const int o    = ot * G + warp;

    // ---- sel-independent prologue: overlaps with sel_kernel via PDL ----
    const size_t rbase = ((size_t)k * OO + o) * II;
    const float4* mrow = reinterpret_cast<const float4*>(mean + rbase);
    const float4* lrow = reinterpret_cast<const float4*>(ls   + rbase);
    float4 mv[4], sv[4];
#pragma unroll
    for (int j = 0; j < 4; j++) {
        mv[j] = mrow[lane + 32 * j];
        float4 l4 = lrow[lane + 32 * j];
        sv[j].x = expf(l4.x); sv[j].y = expf(l4.y);
        sv[j].z = expf(l4.z); sv[j].w = expf(l4.w);
    }

    // ---- wait for sel_kernel's g_cnt/g_list to be visible ----
    cudaGridDependencySynchronize();

    const int cnt   = g_cnt[k];
    const int start = (int)((long long)cnt * slice / P);
    const int end   = (int)((long long)cnt * (slice + 1) / P);
    int idx = start;

    // Odd-length remainder: one single-b iteration.
    if ((end - start) & 1) {
        const int b = g_list[k][idx++];
        const float4* ev = reinterpret_cast<const float4*>(eps + ((size_t)b * OO + o) * II);
        const float4* Xv = reinterpret_cast<const float4*>(X   + (size_t)b * II);
        float4 e4[4], x4[4];
#pragma unroll
        for (int j = 0; j < 4; j++) e4[j] = __ldcs(&ev[lane + 32 * j]);
#pragma unroll
        for (int j = 0; j < 4; j++) x4[j] = Xv[lane + 32 * j];
        float acc = 0.f;
#pragma unroll
        for (int j = 0; j < 4; j++) {
            acc = fmaf(x4[j].x, fmaf(sv[j].x, e4[j].x, mv[j].x), acc);
            acc = fmaf(x4[j].y, fmaf(sv[j].y, e4[j].y, mv[j].y), acc);
            acc = fmaf(x4[j].z, fmaf(sv[j].z, e4[j].z, mv[j].z), acc);
            acc = fmaf(x4[j].w, fmaf(sv[j].w, e4[j].w, mv[j].w), acc);
        }
#pragma unroll
        for (int off = 16; off; off >>= 1)
            acc += __shfl_xor_sync(0xffffffffu, acc, off);
        if (lane == 0) __stcs(&out[(size_t)b * OO + o], acc);
    }

    // Main pairs with index prefetch: 8 eps LDG.128 in flight per warp.
    int b0 = 0, b1 = 0;
    if (idx < end) { b0 = g_list[k][idx]; b1 = g_list[k][idx + 1]; }

    for (; idx < end; idx += 2) {
        const float4* e0 = reinterpret_cast<const float4*>(eps + ((size_t)b0 * OO + o) * II);
        const float4* e1 = reinterpret_cast<const float4*>(eps + ((size_t)b1 * OO + o) * II);
        const float4* x0 = reinterpret_cast<const float4*>(X   + (size_t)b0 * II);
        const float4* x1 = reinterpret_cast<const float4*>(X   + (size_t)b1 * II);

        float4 ea[4], eb[4], xa[4], xb[4];
#pragma unroll
        for (int j = 0; j < 4; j++) ea[j] = __ldcs(&e0[lane + 32 * j]);  // DRAM, evict-first
#pragma unroll
        for (int j = 0; j < 4; j++) eb[j] = __ldcs(&e1[lane + 32 * j]);  // DRAM, evict-first
#pragma unroll
        for (int j = 0; j < 4; j++) xa[j] = x0[lane + 32 * j];           // L1-resident
#pragma unroll
        for (int j = 0; j < 4; j++) xb[j] = x1[lane + 32 * j];           // L1-resident

        const int bc0 = b0, bc1 = b1;
        // Prefetch next pair's indices during the FMA phase.
        if (idx + 2 < end) { b0 = g_list[k][idx + 2]; b1 = g_list[k][idx + 3]; }

        float acc0 = 0.f, acc1 = 0.f;
#pragma unroll
        for (int j = 0; j < 4; j++) {
            acc0 = fmaf(xa[j].x, fmaf(sv[j].x, ea[j].x, mv[j].x), acc0);
            acc1 = fmaf(xb[j].x, fmaf(sv[j].x, eb[j].x, mv[j].x), acc1);
            acc0 = fmaf(xa[j].y, fmaf(sv[j].y, ea[j].y, mv[j].y), acc0);
            acc1 = fmaf(xb[j].y, fmaf(sv[j].y, eb[j].y, mv[j].y), acc1);
            acc0 = fmaf(xa[j].z, fmaf(sv[j].z, ea[j].z, mv[j].z), acc0);
            acc1 = fmaf(xb[j].z, fmaf(sv[j].z, eb[j].z, mv[j].z), acc1);
            acc0 = fmaf(xa[j].w, fmaf(sv[j].w, ea[j].w, mv[j].w), acc0);
            acc1 = fmaf(xb[j].w, fmaf(sv[j].w, eb[j].w, mv[j].w), acc1);
        }
#pragma unroll
        for (int off = 16; off; off >>= 1) {
            acc0 += __shfl_xor_sync(0xffffffffu, acc0, off);
            acc1 += __shfl_xor_sync(0xffffffffu, acc1, off);
        }
        if (lane == 0) {
            __stcs(&out[(size_t)bc0 * OO + o], acc0);
            __stcs(&out[(size_t)bc1 * OO + o], acc1);
        }
    }
}

// ---------------------------------------------------------------------------
// Inputs (metadata order): X[B,I], mix_weights[K], mean[K,O,I],
//                          log_sigma[K,O,I], u_gumbel[B,K], eps[B,O,I]
// Output: float32 [B,O]
// ---------------------------------------------------------------------------
extern "C" void kernel_launch(void* const* d_in, const int* in_sizes, int n_in,
                              void* d_out, int out_size) {
    const float* X    = (const float*)d_in[0];
    const float* mw   = (const float*)d_in[1];
    const float* mean = (const float*)d_in[2];
    const float* ls   = (const float*)d_in[3];
    const float* u    = (const float*)d_in[4];
    const float* eps  = (const float*)d_in[5];
    float* out        = (float*)d_out;

    sel_kernel<<<1, 1024>>>(mw, u);

    // PDL launch (implicit trigger — the early trigger measurably hurt):
    // main's prologue overlaps sel's tail; body gated by
    // cudaGridDependencySynchronize().
    cudaLaunchConfig_t cfg = {};
    cfg.gridDim  = dim3(KK * OT * P);
    cfg.blockDim = dim3(256);
    cudaLaunchAttribute attr[1];
    attr[0].id = cudaLaunchAttributeProgrammaticStreamSerialization;
    attr[0].val.programmaticStreamSerializationAllowed = 1;
    cfg.attrs    = attr;
    cfg.numAttrs = 1;
    cudaLaunchKernelEx(&cfg, main_kernel, X, mean, ls, eps, out);
}

// round 17
// speedup vs baseline: 1.0217x; 1.0081x over previous
#include <cuda_runtime.h>
#include <math.h>

#define BB 2048
#define KK 8
#define OO 256
#define II 512

#define G  8              // o's per block (one warp each)
#define OT (OO / G)       // 32 o-tiles
#define P  8              // b-slices per (k, o-tile)  (measured optimum)

// Scratch (no allocs allowed)
__device__ int g_cnt[KK];
__device__ int g_list[KK][BB];

// ---------------------------------------------------------------------------
// 1) Selection + per-k compaction.
//    Hard gumbel-softmax forward value == one_hot(argmax_k(mw[k]+g_k)).
//    FAST PATH: uniform mw (reference uses full(1/K)) + g(u) strictly
//    increasing in u  =>  argmax_k u[b,k], no logarithms. u rows loaded as
//    2x float4. Exact-gumbel fallback retained for non-uniform mw.
//    PDL trigger fires AFTER the argmax/atomic phase (only the list writes
//    remain) so main's blocks launch/prologue overlap sel's tail without
//    the full-kernel polling contention that hurt in R15.
// ---------------------------------------------------------------------------
__global__ __launch_bounds__(1024)
void sel_kernel(const float* __restrict__ mw,
                const float* __restrict__ u) {
    __shared__ int scnt[KK];
    const int tid = threadIdx.x;
    if (tid < KK) scnt[tid] = 0;

    // All-equal check on mw (8 values, L1-broadcast).
    float m0 = mw[0];
    bool uniform = true;
#pragma unroll
    for (int k = 1; k < KK; k++) uniform &= (mw[k] == m0);

    __syncthreads();

    int myk[BB / 1024], mypos[BB / 1024];
#pragma unroll
    for (int r = 0; r < BB / 1024; r++) {
        const int b = tid + 1024 * r;
        const float4* uv = reinterpret_cast<const float4*>(u + b * KK);
        const float4 a = uv[0];
        const float4 c = uv[1];
        float v[KK] = {a.x, a.y, a.z, a.w, c.x, c.y, c.z, c.w};

        int bi = 0;
        if (uniform) {
            // Monotone shortcut: argmax of raw uniforms (strict > == first max).
            float best = -INFINITY;
#pragma unroll
            for (int k = 0; k < KK; k++)
                if (v[k] > best) { best = v[k]; bi = k; }
        } else {
            float best = -INFINITY;
#pragma unroll
            for (int k = 0; k < KK; k++) {
                float g = -logf(-logf(v[k] + 1e-10f) + 1e-10f);
                float t = mw[k] + g;
                if (t > best) { best = t; bi = k; }
            }
        }
        myk[r]   = bi;
        mypos[r] = atomicAdd(&scnt[bi], 1);
    }
    __syncthreads();

    // Only the compacted-list writes remain (~hundreds of ns): let the
    // dependent kernel start launching now.
    cudaTriggerProgrammaticLaunchCompletion();

#pragma unroll
    for (int r = 0; r < BB / 1024; r++)
        g_list[myk[r]][mypos[r]] = tid + 1024 * r;
    if (tid < KK) g_cnt[tid] = scnt[tid];
}

// ---------------------------------------------------------------------------
// 2) out[b,o] = sum_i X[b,i] * fmaf(exp(ls[k,o,i]), eps[b,o,i], mean[k,o,i])
//    Measured-optimal structure: 120 regs, occ 2, staged X arrays, b-pairs
//    with 8 eps LDG.128 batched, dual 5-level butterfly reduce, g_list
//    index prefetch. eps via __ldcs; out via __stcs; PDL gates g_cnt/g_list.
// ---------------------------------------------------------------------------
__global__ __launch_bounds__(256, 2)
void main_kernel(const float* __restrict__ X,
                 const float* __restrict__ mean,
                 const float* __restrict__ ls,
                 const float* __restrict__ eps,
                 float*       __restrict__ out) {
    const int blk   = blockIdx.x;
    const int slice = blk % P;
    const int ot    = (blk / P) % OT;
    const int k     = blk / (P * OT);

    const int warp = threadIdx.x >> 5;
    const int lane = threadIdx.x & 31;
    const int o    = ot * G + warp;

    // ---- sel-independent prologue: overlaps with sel_kernel via PDL ----
    const size_t rbase = ((size_t)k * OO + o) * II;
    const float4* mrow = reinterpret_cast<const float4*>(mean + rbase);
    const float4* lrow = reinterpret_cast<const float4*>(ls   + rbase);
    float4 mv[4], sv[4];
#pragma unroll
    for (int j = 0; j < 4; j++) {
        mv[j] = mrow[lane + 32 * j];
        float4 l4 = lrow[lane + 32 * j];
        sv[j].x = expf(l4.x); sv[j].y = expf(l4.y);
        sv[j].z = expf(l4.z); sv[j].w = expf(l4.w);
    }

    // ---- wait for sel_kernel's g_cnt/g_list to be visible ----
    cudaGridDependencySynchronize();

    const int cnt   = g_cnt[k];
    const int start = (int)((long long)cnt * slice / P);
    const int end   = (int)((long long)cnt * (slice + 1) / P);
    int idx = start;

    // Odd-length remainder: one single-b iteration.
    if ((end - start) & 1) {
        const int b = g_list[k][idx++];
        const float4* ev = reinterpret_cast<const float4*>(eps + ((size_t)b * OO + o) * II);
        const float4* Xv = reinterpret_cast<const float4*>(X   + (size_t)b * II);
        float4 e4[4], x4[4];
#pragma unroll
        for (int j = 0; j < 4; j++) e4[j] = __ldcs(&ev[lane + 32 * j]);
#pragma unroll
        for (int j = 0; j < 4; j++) x4[j] = Xv[lane + 32 * j];
        float acc = 0.f;
#pragma unroll
        for (int j = 0; j < 4; j++) {
            acc = fmaf(x4[j].x, fmaf(sv[j].x, e4[j].x, mv[j].x), acc);
            acc = fmaf(x4[j].y, fmaf(sv[j].y, e4[j].y, mv[j].y), acc);
            acc = fmaf(x4[j].z, fmaf(sv[j].z, e4[j].z, mv[j].z), acc);
            acc = fmaf(x4[j].w, fmaf(sv[j].w, e4[j].w, mv[j].w), acc);
        }
#pragma unroll
        for (int off = 16; off; off >>= 1)
            acc += __shfl_xor_sync(0xffffffffu, acc, off);
        if (lane == 0) __stcs(&out[(size_t)b * OO + o], acc);
    }

    // Main pairs with index prefetch: 8 eps LDG.128 in flight per warp.
    int b0 = 0, b1 = 0;
    if (idx < end) { b0 = g_list[k][idx]; b1 = g_list[k][idx + 1]; }

    for (; idx < end; idx += 2) {
        const float4* e0 = reinterpret_cast<const float4*>(eps + ((size_t)b0 * OO + o) * II);
        const float4* e1 = reinterpret_cast<const float4*>(eps + ((size_t)b1 * OO + o) * II);
        const float4* x0 = reinterpret_cast<const float4*>(X   + (size_t)b0 * II);
        const float4* x1 = reinterpret_cast<const float4*>(X   + (size_t)b1 * II);

        float4 ea[4], eb[4], xa[4], xb[4];
#pragma unroll
        for (int j = 0; j < 4; j++) ea[j] = __ldcs(&e0[lane + 32 * j]);  // DRAM, evict-first
#pragma unroll
        for (int j = 0; j < 4; j++) eb[j] = __ldcs(&e1[lane + 32 * j]);  // DRAM, evict-first
#pragma unroll
        for (int j = 0; j < 4; j++) xa[j] = x0[lane + 32 * j];           // L1-resident
#pragma unroll
        for (int j = 0; j < 4; j++) xb[j] = x1[lane + 32 * j];           // L1-resident

        const int bc0 = b0, bc1 = b1;
        // Prefetch next pair's indices during the FMA phase.
        if (idx + 2 < end) { b0 = g_list[k][idx + 2]; b1 = g_list[k][idx + 3]; }

        float acc0 = 0.f, acc1 = 0.f;
#pragma unroll
        for (int j = 0; j < 4; j++) {
            acc0 = fmaf(xa[j].x, fmaf(sv[j].x, ea[j].x, mv[j].x), acc0);
            acc1 = fmaf(xb[j].x, fmaf(sv[j].x, eb[j].x, mv[j].x), acc1);
            acc0 = fmaf(xa[j].y, fmaf(sv[j].y, ea[j].y, mv[j].y), acc0);
            acc1 = fmaf(xb[j].y, fmaf(sv[j].y, eb[j].y, mv[j].y), acc1);
            acc0 = fmaf(xa[j].z, fmaf(sv[j].z, ea[j].z, mv[j].z), acc0);
            acc1 = fmaf(xb[j].z, fmaf(sv[j].z, eb[j].z, mv[j].z), acc1);
            acc0 = fmaf(xa[j].w, fmaf(sv[j].w, ea[j].w, mv[j].w), acc0);
            acc1 = fmaf(xb[j].w, fmaf(sv[j].w, eb[j].w, mv[j].w), acc1);
        }
#pragma unroll
        for (int off = 16; off; off >>= 1) {
            acc0 += __shfl_xor_sync(0xffffffffu, acc0, off);
            acc1 += __shfl_xor_sync(0xffffffffu, acc1, off);
        }
        if (lane == 0) {
            __stcs(&out[(size_t)bc0 * OO + o], acc0);
            __stcs(&out[(size_t)bc1 * OO + o], acc1);
        }
    }
}

// ---------------------------------------------------------------------------
// Inputs (metadata order): X[B,I], mix_weights[K], mean[K,O,I],
//                          log_sigma[K,O,I], u_gumbel[B,K], eps[B,O,I]
// Output: float32 [B,O]
// ---------------------------------------------------------------------------
extern "C" void kernel_launch(void* const* d_in, const int* in_sizes, int n_in,
                              void* d_out, int out_size) {
    const float* X    = (const float*)d_in[0];
    const float* mw   = (const float*)d_in[1];
    const float* mean = (const float*)d_in[2];
    const float* ls   = (const float*)d_in[3];
    const float* u    = (const float*)d_in[4];
    const float* eps  = (const float*)d_in[5];
    float* out        = (float*)d_out;

    sel_kernel<<<1, 1024>>>(mw, u);

    // PDL launch: sel fires its trigger just before its final writes, so
    // main's blocks launch + run their prologue under sel's tail; the body
    // is gated by cudaGridDependencySynchronize().
    cudaLaunchConfig_t cfg = {};
    cfg.gridDim  = dim3(KK * OT * P);
    cfg.blockDim = dim3(256);
    cudaLaunchAttribute attr[1];
    attr[0].id = cudaLaunchAttributeProgrammaticStreamSerialization;
    attr[0].val.programmaticStreamSerializationAllowed = 1;
    cfg.attrs    = attr;
    cfg.numAttrs = 1;
    cudaLaunchKernelEx(&cfg, main_kernel, X, mean, ls, eps, out);
}